// round 13
// baseline (speedup 1.0000x reference)
#include <cuda_runtime.h>
#include <cuda_fp16.h>
#include <cstdint>

#define DIM 128
#define NTH 384
#define WARPS 12
#define ROWS_PER_WARP 32
#define PI_F 3.14159265358979323846f

// ---- smem: two 128x128 fp16 weight tiles (swizzled) + biases ----
#define OFF_W1  0
#define OFF_W2  32768
#define OFF_B1  65536
#define OFF_B2  66048
#define SMEM_TOTAL 66560

__device__ __forceinline__ uint32_t swz(int row, int kElem) {
    return (uint32_t)(row * 256) + (((uint32_t)(kElem * 2)) ^ (uint32_t)((row & 7) << 4));
}

__device__ __forceinline__ uint32_t smem_u32(const void* p) {
    uint32_t a;
    asm("{ .reg .u64 t; cvta.to.shared.u64 t, %1; cvt.u32.u64 %0, t; }" : "=r"(a) : "l"(p));
    return a;
}

__device__ __forceinline__ void ldsm4(uint32_t& r0, uint32_t& r1, uint32_t& r2, uint32_t& r3,
                                      uint32_t addr) {
    asm volatile("ldmatrix.sync.aligned.m8n8.x4.shared.b16 {%0,%1,%2,%3}, [%4];"
                 : "=r"(r0), "=r"(r1), "=r"(r2), "=r"(r3) : "r"(addr));
}

__device__ __forceinline__ void mma16816(float* c, const uint32_t* a, uint32_t b0, uint32_t b1) {
    asm volatile(
        "mma.sync.aligned.m16n8k16.row.col.f32.f16.f16.f32 "
        "{%0,%1,%2,%3}, {%4,%5,%6,%7}, {%8,%9}, {%0,%1,%2,%3};"
        : "+f"(c[0]), "+f"(c[1]), "+f"(c[2]), "+f"(c[3])
        : "r"(a[0]), "r"(a[1]), "r"(a[2]), "r"(a[3]), "r"(b0), "r"(b1));
}

__device__ __forceinline__ uint32_t pack2h(float x0, float x1) {
    return ((uint32_t)__half_as_ushort(__float2half_rn(x1)) << 16) |
           (uint32_t)__half_as_ushort(__float2half_rn(x0));
}

__device__ __forceinline__ void store_h2(char* sm, int base, int row, int k,
                                         float x0, float x1) {
    *(uint32_t*)(sm + base + swz(row, k)) = pack2h(x0, x1);
}

__device__ __forceinline__ float silu_f(float z) {
    return __fdividef(z, 1.0f + __expf(-z));
}
__device__ __forceinline__ float emb_f(float tv, float p1, float p2, float d) {
    return tv * (__cosf(d * p1) + __sinf(d * p2));
}

__global__ void __launch_bounds__(NTH, 1)
fused_timestep_mlp_ns(const float* __restrict__ t,
                      const float* __restrict__ W1,
                      const float* __restrict__ b1,
                      const float* __restrict__ W2,
                      const float* __restrict__ b2,
                      float* __restrict__ out,
                      int n_chunks) {
    extern __shared__ char sm[];
    const uint32_t sb = smem_u32(sm);
    const int tid = threadIdx.x;
    const int wid = tid >> 5;
    const int lane = tid & 31;

    // ---- weight init: fp16 swizzled tiles; biases ----
    for (int e = tid * 4; e < DIM * DIM; e += NTH * 4) {
        const int row = e >> 7, k = e & 127;
        const float4 v1 = *(const float4*)(W1 + e);
        store_h2(sm, OFF_W1, row, k,     v1.x, v1.y);
        store_h2(sm, OFF_W1, row, k + 2, v1.z, v1.w);
        const float4 v2 = *(const float4*)(W2 + e);
        store_h2(sm, OFF_W2, row, k,     v2.x, v2.y);
        store_h2(sm, OFF_W2, row, k + 2, v2.z, v2.w);
    }
    if (tid < 128)      ((float*)(sm + OFF_B1))[tid] = b1[tid];
    else if (tid < 256) ((float*)(sm + OFF_B2))[tid - 128] = b2[tid - 128];
    __syncthreads();  // only sync in the kernel

    const float* sB1 = (const float*)(sm + OFF_B1);
    const float* sB2 = (const float*)(sm + OFF_B2);

    // lane geometry
    const int r0 = lane >> 2;                 // frag row (and +8)
    const int kp = (lane & 3) * 2;            // frag col-pair base
    const int g = lane >> 3, i = lane & 7;
    const int wRowLoc = ((g >> 1) << 3) + i;  // B-frag n within 16
    const int wKoff   = (g & 1) << 3;         // B-frag k half

    for (int chunk = blockIdx.x * WARPS + wid; chunk < n_chunks;
         chunk += gridDim.x * WARPS) {
        const int rowBase = chunk * ROWS_PER_WARP;

        float tv[2][2], p1[2][2], p2[2][2];
#pragma unroll
        for (int mt = 0; mt < 2; ++mt) {
            tv[mt][0] = t[rowBase + mt * 16 + r0];
            tv[mt][1] = t[rowBase + mt * 16 + r0 + 8];
#pragma unroll
            for (int u = 0; u < 2; ++u) {
                p1[mt][u] = tv[mt][u] * (PI_F / 128.0f);
                p2[mt][u] = (1.0f - tv[mt][u]) * (PI_F / 128.0f);
            }
        }

        uint32_t ha[2][8][4];   // layer-2 A-frags (filled per n-half)
        float acc[2][8][4];     // reused across all 4 passes

        // ======== GEMM1: two n-half passes ========
#pragma unroll
        for (int nh = 0; nh < 2; ++nh) {
#pragma unroll
            for (int mt = 0; mt < 2; ++mt)
#pragma unroll
                for (int nt = 0; nt < 8; ++nt)
#pragma unroll
                    for (int q = 0; q < 4; ++q) acc[mt][nt][q] = 0.0f;

#pragma unroll
            for (int ks = 0; ks < 8; ++ks) {
                const int kb = ks * 16;
                const float dA = (float)(kb + kp), dB = dA + 1.0f;
                const float dC = dA + 8.0f,       dD = dA + 9.0f;
                uint32_t a[2][4];
#pragma unroll
                for (int mt = 0; mt < 2; ++mt) {
                    a[mt][0] = pack2h(emb_f(tv[mt][0], p1[mt][0], p2[mt][0], dA),
                                      emb_f(tv[mt][0], p1[mt][0], p2[mt][0], dB));
                    a[mt][1] = pack2h(emb_f(tv[mt][1], p1[mt][1], p2[mt][1], dA),
                                      emb_f(tv[mt][1], p1[mt][1], p2[mt][1], dB));
                    a[mt][2] = pack2h(emb_f(tv[mt][0], p1[mt][0], p2[mt][0], dC),
                                      emb_f(tv[mt][0], p1[mt][0], p2[mt][0], dD));
                    a[mt][3] = pack2h(emb_f(tv[mt][1], p1[mt][1], p2[mt][1], dC),
                                      emb_f(tv[mt][1], p1[mt][1], p2[mt][1], dD));
                }
#pragma unroll
                for (int np = 0; np < 4; ++np) {
                    const uint32_t wa = swz(nh * 64 + np * 16 + wRowLoc, kb + wKoff);
                    uint32_t b[4];
                    ldsm4(b[0], b[1], b[2], b[3], sb + OFF_W1 + wa);
#pragma unroll
                    for (int mt = 0; mt < 2; ++mt) {
                        mma16816(acc[mt][2 * np],     a[mt], b[0], b[1]);
                        mma16816(acc[mt][2 * np + 1], a[mt], b[2], b[3]);
                    }
                }
            }

            // convert this n-half: bias + silu -> ha[mt][nh*4 + j]
#pragma unroll
            for (int j = 0; j < 4; ++j) {
                const int colbase = nh * 64 + j * 16;
                const float2 bA = *(const float2*)(sB1 + colbase + kp);
                const float2 bB = *(const float2*)(sB1 + colbase + 8 + kp);
#pragma unroll
                for (int mt = 0; mt < 2; ++mt) {
                    const float* c0 = acc[mt][2 * j];
                    const float* c1 = acc[mt][2 * j + 1];
                    ha[mt][nh * 4 + j][0] = pack2h(silu_f(c0[0] + bA.x), silu_f(c0[1] + bA.y));
                    ha[mt][nh * 4 + j][1] = pack2h(silu_f(c0[2] + bA.x), silu_f(c0[3] + bA.y));
                    ha[mt][nh * 4 + j][2] = pack2h(silu_f(c1[0] + bB.x), silu_f(c1[1] + bB.y));
                    ha[mt][nh * 4 + j][3] = pack2h(silu_f(c1[2] + bB.x), silu_f(c1[3] + bB.y));
                }
            }
        }

        // ======== GEMM2: two n-half passes ========
#pragma unroll
        for (int nh = 0; nh < 2; ++nh) {
#pragma unroll
            for (int mt = 0; mt < 2; ++mt)
#pragma unroll
                for (int nt = 0; nt < 8; ++nt)
#pragma unroll
                    for (int q = 0; q < 4; ++q) acc[mt][nt][q] = 0.0f;

#pragma unroll
            for (int ks = 0; ks < 8; ++ks) {
                const int kb = ks * 16;
#pragma unroll
                for (int np = 0; np < 4; ++np) {
                    const uint32_t wa = swz(nh * 64 + np * 16 + wRowLoc, kb + wKoff);
                    uint32_t b[4];
                    ldsm4(b[0], b[1], b[2], b[3], sb + OFF_W2 + wa);
#pragma unroll
                    for (int mt = 0; mt < 2; ++mt) {
                        mma16816(acc[mt][2 * np],     ha[mt][ks], b[0], b[1]);
                        mma16816(acc[mt][2 * np + 1], ha[mt][ks], b[2], b[3]);
                    }
                }
            }

            // store this n-half: bias + silu -> gmem
#pragma unroll
            for (int mt = 0; mt < 2; ++mt) {
                float* o0 = out + (size_t)(rowBase + mt * 16 + r0) * DIM;
                float* o1 = out + (size_t)(rowBase + mt * 16 + r0 + 8) * DIM;
#pragma unroll
                for (int nt = 0; nt < 8; ++nt) {
                    const int c = nh * 64 + nt * 8 + kp;
                    const float2 bb = *(const float2*)(sB2 + c);
                    const float* a4 = acc[mt][nt];
                    *(float2*)(o0 + c) = make_float2(silu_f(a4[0] + bb.x), silu_f(a4[1] + bb.y));
                    *(float2*)(o1 + c) = make_float2(silu_f(a4[2] + bb.x), silu_f(a4[3] + bb.y));
                }
            }
        }
    }
}

extern "C" void kernel_launch(void* const* d_in, const int* in_sizes, int n_in,
                              void* d_out, int out_size) {
    const float* t  = (const float*)d_in[0];
    const float* W1 = (const float*)d_in[1];
    const float* b1 = (const float*)d_in[2];
    const float* W2 = (const float*)d_in[3];
    const float* b2 = (const float*)d_in[4];
    float* out = (float*)d_out;

    const int B = in_sizes[0];
    const int n_chunks = B / ROWS_PER_WARP;

    int nsm = 148;
    cudaDeviceGetAttribute(&nsm, cudaDevAttrMultiProcessorCount, 0);

    cudaFuncSetAttribute(fused_timestep_mlp_ns,
                         cudaFuncAttributeMaxDynamicSharedMemorySize, SMEM_TOTAL);

    fused_timestep_mlp_ns<<<nsm, NTH, SMEM_TOTAL>>>(t, W1, b1, W2, b2, out, n_chunks);
}

// round 14
// speedup vs baseline: 1.3172x; 1.3172x over previous
#include <cuda_runtime.h>
#include <cuda_fp16.h>
#include <cstdint>

#define DIM 128
#define NTH 512
#define WARPS 16
#define PI_F 3.14159265358979323846f

// ---- smem: two 128x128 fp16 weight tiles (swizzled) + biases ----
#define OFF_W1  0
#define OFF_W2  32768
#define OFF_B1  65536
#define OFF_B2  66048
#define SMEM_TOTAL 66560

__device__ __forceinline__ uint32_t swz(int row, int kElem) {
    return (uint32_t)(row * 256) + (((uint32_t)(kElem * 2)) ^ (uint32_t)((row & 7) << 4));
}

__device__ __forceinline__ uint32_t smem_u32(const void* p) {
    uint32_t a;
    asm("{ .reg .u64 t; cvta.to.shared.u64 t, %1; cvt.u32.u64 %0, t; }" : "=r"(a) : "l"(p));
    return a;
}

__device__ __forceinline__ void ldsm4(uint32_t& r0, uint32_t& r1, uint32_t& r2, uint32_t& r3,
                                      uint32_t addr) {
    asm volatile("ldmatrix.sync.aligned.m8n8.x4.shared.b16 {%0,%1,%2,%3}, [%4];"
                 : "=r"(r0), "=r"(r1), "=r"(r2), "=r"(r3) : "r"(addr));
}

__device__ __forceinline__ void mma16816(float* c, const uint32_t* a, uint32_t b0, uint32_t b1) {
    asm volatile(
        "mma.sync.aligned.m16n8k16.row.col.f32.f16.f16.f32 "
        "{%0,%1,%2,%3}, {%4,%5,%6,%7}, {%8,%9}, {%0,%1,%2,%3};"
        : "+f"(c[0]), "+f"(c[1]), "+f"(c[2]), "+f"(c[3])
        : "r"(a[0]), "r"(a[1]), "r"(a[2]), "r"(a[3]), "r"(b0), "r"(b1));
}

__device__ __forceinline__ uint32_t pack2h(float x0, float x1) {
    return ((uint32_t)__half_as_ushort(__float2half_rn(x1)) << 16) |
           (uint32_t)__half_as_ushort(__float2half_rn(x0));
}

__device__ __forceinline__ void store_h2(char* sm, int base, int row, int k,
                                         float x0, float x1) {
    *(uint32_t*)(sm + base + swz(row, k)) = pack2h(x0, x1);
}

__device__ __forceinline__ float silu_f(float z) {
    return __fdividef(z, 1.0f + __expf(-z));
}
__device__ __forceinline__ float emb_f(float tv, float p1, float p2, float d) {
    return tv * (__cosf(d * p1) + __sinf(d * p2));
}

__global__ void __launch_bounds__(NTH, 1)
fused_timestep_mlp_v14(const float* __restrict__ t,
                       const float* __restrict__ W1,
                       const float* __restrict__ b1,
                       const float* __restrict__ W2,
                       const float* __restrict__ b2,
                       float* __restrict__ out,
                       int n_chunks) {
    extern __shared__ char sm[];
    const uint32_t sb = smem_u32(sm);
    const int tid = threadIdx.x;
    const int wid = tid >> 5;
    const int lane = tid & 31;

    // ---- weight init: fp16 swizzled tiles; biases ----
    for (int e = tid * 4; e < DIM * DIM; e += NTH * 4) {
        const int row = e >> 7, k = e & 127;
        const float4 v1 = *(const float4*)(W1 + e);
        store_h2(sm, OFF_W1, row, k,     v1.x, v1.y);
        store_h2(sm, OFF_W1, row, k + 2, v1.z, v1.w);
        const float4 v2 = *(const float4*)(W2 + e);
        store_h2(sm, OFF_W2, row, k,     v2.x, v2.y);
        store_h2(sm, OFF_W2, row, k + 2, v2.z, v2.w);
    }
    if (tid < 128)      ((float*)(sm + OFF_B1))[tid] = b1[tid];
    else if (tid < 256) ((float*)(sm + OFF_B2))[tid - 128] = b2[tid - 128];
    __syncthreads();  // only sync in the kernel

    const float* sB1 = (const float*)(sm + OFF_B1);
    const float* sB2 = (const float*)(sm + OFF_B2);

    // lane geometry
    const int r0 = lane >> 2;                 // frag row (and +8)
    const int kp = (lane & 3) * 2;            // frag col-pair base
    const int g = lane >> 3, i = lane & 7;
    const int wRowLoc = ((g >> 1) << 3) + i;  // B-frag n within 16
    const int wKoff   = (g & 1) << 3;         // B-frag k half

    for (int chunk = blockIdx.x * WARPS + wid; chunk < n_chunks;
         chunk += gridDim.x * WARPS) {
        const int rowBase = chunk * 16;

        // ---- emb A-frags, built once: ea[ks][4] ----
        uint32_t ea[8][4];
        {
            const float tv0 = t[rowBase + r0];
            const float tv1 = t[rowBase + r0 + 8];
            const float p10 = tv0 * (PI_F / 128.0f), p20 = (1.0f - tv0) * (PI_F / 128.0f);
            const float p11 = tv1 * (PI_F / 128.0f), p21 = (1.0f - tv1) * (PI_F / 128.0f);
#pragma unroll
            for (int ks = 0; ks < 8; ++ks) {
                const float dA = (float)(ks * 16 + kp), dB = dA + 1.0f;
                const float dC = dA + 8.0f,             dD = dA + 9.0f;
                ea[ks][0] = pack2h(emb_f(tv0, p10, p20, dA), emb_f(tv0, p10, p20, dB));
                ea[ks][1] = pack2h(emb_f(tv1, p11, p21, dA), emb_f(tv1, p11, p21, dB));
                ea[ks][2] = pack2h(emb_f(tv0, p10, p20, dC), emb_f(tv0, p10, p20, dD));
                ea[ks][3] = pack2h(emb_f(tv1, p11, p21, dC), emb_f(tv1, p11, p21, dD));
            }
        }

        uint32_t ha[8][4];   // layer-2 A-frags
        float acc[8][4];     // reused across all 4 passes

        // ======== GEMM1: two 64-col passes ========
#pragma unroll
        for (int nh = 0; nh < 2; ++nh) {
#pragma unroll
            for (int nt = 0; nt < 8; ++nt)
#pragma unroll
                for (int q = 0; q < 4; ++q) acc[nt][q] = 0.0f;

#pragma unroll
            for (int ks = 0; ks < 8; ++ks) {
                const int kb = ks * 16;
#pragma unroll
                for (int pp = 0; pp < 2; ++pp) {       // pairs of 16-col groups
                    uint32_t b0[4], b1r[4];
                    const int np0 = pp * 2, np1 = pp * 2 + 1;
                    ldsm4(b0[0], b0[1], b0[2], b0[3],
                          sb + OFF_W1 + swz(nh * 64 + np0 * 16 + wRowLoc, kb + wKoff));
                    ldsm4(b1r[0], b1r[1], b1r[2], b1r[3],
                          sb + OFF_W1 + swz(nh * 64 + np1 * 16 + wRowLoc, kb + wKoff));
                    mma16816(acc[2 * np0],     ea[ks], b0[0],  b0[1]);
                    mma16816(acc[2 * np0 + 1], ea[ks], b0[2],  b0[3]);
                    mma16816(acc[2 * np1],     ea[ks], b1r[0], b1r[1]);
                    mma16816(acc[2 * np1 + 1], ea[ks], b1r[2], b1r[3]);
                }
            }

            // convert this 64-col half: bias + silu -> ha[nh*4 + j]
#pragma unroll
            for (int j = 0; j < 4; ++j) {
                const int colbase = nh * 64 + j * 16;
                const float2 bA = *(const float2*)(sB1 + colbase + kp);
                const float2 bB = *(const float2*)(sB1 + colbase + 8 + kp);
                const float* c0 = acc[2 * j];
                const float* c1 = acc[2 * j + 1];
                ha[nh * 4 + j][0] = pack2h(silu_f(c0[0] + bA.x), silu_f(c0[1] + bA.y));
                ha[nh * 4 + j][1] = pack2h(silu_f(c0[2] + bA.x), silu_f(c0[3] + bA.y));
                ha[nh * 4 + j][2] = pack2h(silu_f(c1[0] + bB.x), silu_f(c1[1] + bB.y));
                ha[nh * 4 + j][3] = pack2h(silu_f(c1[2] + bB.x), silu_f(c1[3] + bB.y));
            }
        }

        // ======== GEMM2: two 64-col passes ========
        float* o0 = out + (size_t)(rowBase + r0) * DIM;
        float* o1 = out + (size_t)(rowBase + r0 + 8) * DIM;
#pragma unroll
        for (int nh = 0; nh < 2; ++nh) {
#pragma unroll
            for (int nt = 0; nt < 8; ++nt)
#pragma unroll
                for (int q = 0; q < 4; ++q) acc[nt][q] = 0.0f;

#pragma unroll
            for (int ks = 0; ks < 8; ++ks) {
                const int kb = ks * 16;
#pragma unroll
                for (int pp = 0; pp < 2; ++pp) {
                    uint32_t b0[4], b1r[4];
                    const int np0 = pp * 2, np1 = pp * 2 + 1;
                    ldsm4(b0[0], b0[1], b0[2], b0[3],
                          sb + OFF_W2 + swz(nh * 64 + np0 * 16 + wRowLoc, kb + wKoff));
                    ldsm4(b1r[0], b1r[1], b1r[2], b1r[3],
                          sb + OFF_W2 + swz(nh * 64 + np1 * 16 + wRowLoc, kb + wKoff));
                    mma16816(acc[2 * np0],     ha[ks], b0[0],  b0[1]);
                    mma16816(acc[2 * np0 + 1], ha[ks], b0[2],  b0[3]);
                    mma16816(acc[2 * np1],     ha[ks], b1r[0], b1r[1]);
                    mma16816(acc[2 * np1 + 1], ha[ks], b1r[2], b1r[3]);
                }
            }

            // store this 64-col half: bias + silu -> gmem
#pragma unroll
            for (int nt = 0; nt < 8; ++nt) {
                const int c = nh * 64 + nt * 8 + kp;
                const float2 bb = *(const float2*)(sB2 + c);
                const float* a4 = acc[nt];
                *(float2*)(o0 + c) = make_float2(silu_f(a4[0] + bb.x), silu_f(a4[1] + bb.y));
                *(float2*)(o1 + c) = make_float2(silu_f(a4[2] + bb.x), silu_f(a4[3] + bb.y));
            }
        }
    }
}

extern "C" void kernel_launch(void* const* d_in, const int* in_sizes, int n_in,
                              void* d_out, int out_size) {
    const float* t  = (const float*)d_in[0];
    const float* W1 = (const float*)d_in[1];
    const float* b1 = (const float*)d_in[2];
    const float* W2 = (const float*)d_in[3];
    const float* b2 = (const float*)d_in[4];
    float* out = (float*)d_out;

    const int B = in_sizes[0];
    const int n_chunks = B / 16;

    int nsm = 148;
    cudaDeviceGetAttribute(&nsm, cudaDevAttrMultiProcessorCount, 0);

    cudaFuncSetAttribute(fused_timestep_mlp_v14,
                         cudaFuncAttributeMaxDynamicSharedMemorySize, SMEM_TOTAL);

    fused_timestep_mlp_v14<<<nsm, NTH, SMEM_TOTAL>>>(t, W1, b1, W2, b2, out, n_chunks);
}

// round 15
// speedup vs baseline: 1.3995x; 1.0624x over previous
#include <cuda_runtime.h>
#include <cuda_fp16.h>
#include <cstdint>

#define DIM 128
#define NTH 512
#define WARPS 16
#define PI_F 3.14159265358979323846f

// ---- smem: two packed-tile fp16 weight tiles (32 KB each) + biases ----
#define OFF_W1  0
#define OFF_W2  32768
#define OFF_B1  65536
#define OFF_B2  66048
#define SMEM_TOTAL 66560

// packed core-matrix layout: W[128n][128k] fp16 stored as 16x16 grid of
// 8x8 matrices; matrix (nt,kt) occupies contiguous 128B at ((kt*16)+nt)*128.
// Within a matrix: row r (n), col c (k) at r*16 + c*2.
__device__ __forceinline__ uint32_t w_off(int n, int k) {
    return (uint32_t)((((k >> 3) << 4) + (n >> 3)) * 128 + (n & 7) * 16 + (k & 7) * 2);
}

__device__ __forceinline__ uint32_t smem_u32(const void* p) {
    uint32_t a;
    asm("{ .reg .u64 t; cvta.to.shared.u64 t, %1; cvt.u32.u64 %0, t; }" : "=r"(a) : "l"(p));
    return a;
}

__device__ __forceinline__ void ldsm4(uint32_t& r0, uint32_t& r1, uint32_t& r2, uint32_t& r3,
                                      uint32_t addr) {
    asm volatile("ldmatrix.sync.aligned.m8n8.x4.shared.b16 {%0,%1,%2,%3}, [%4];"
                 : "=r"(r0), "=r"(r1), "=r"(r2), "=r"(r3) : "r"(addr));
}

__device__ __forceinline__ void mma16816(float* c, const uint32_t* a, uint32_t b0, uint32_t b1) {
    asm volatile(
        "mma.sync.aligned.m16n8k16.row.col.f32.f16.f16.f32 "
        "{%0,%1,%2,%3}, {%4,%5,%6,%7}, {%8,%9}, {%0,%1,%2,%3};"
        : "+f"(c[0]), "+f"(c[1]), "+f"(c[2]), "+f"(c[3])
        : "r"(a[0]), "r"(a[1]), "r"(a[2]), "r"(a[3]), "r"(b0), "r"(b1));
}

__device__ __forceinline__ uint32_t pack2h(float x0, float x1) {
    uint32_t r;
    asm("cvt.rn.f16x2.f32 %0, %1, %2;" : "=r"(r) : "f"(x1), "f"(x0));
    return r;
}

// silu on a packed fp16 pair via tanh.approx.f16x2:
// silu(z) = z * 0.5 * (1 + tanh(z/2))
__device__ __forceinline__ uint32_t h2_silu(float z0, float z1) {
    const uint32_t zh = pack2h(z0, z1);
    const uint32_t half2c = 0x38003800u;  // (0.5, 0.5) fp16x2
    uint32_t t, s, r;
    asm("mul.rn.f16x2 %0, %1, %2;" : "=r"(t) : "r"(zh), "r"(half2c));
    asm("tanh.approx.f16x2 %0, %1;" : "=r"(t) : "r"(t));
    asm("fma.rn.f16x2 %0, %1, %2, %2;" : "=r"(s) : "r"(t), "r"(half2c));
    asm("mul.rn.f16x2 %0, %1, %2;" : "=r"(r) : "r"(zh), "r"(s));
    return r;
}

__device__ __forceinline__ float silu_f(float z) {
    return __fdividef(z, 1.0f + __expf(-z));
}
__device__ __forceinline__ float emb_f(float tv, float p1, float p2, float d) {
    return tv * (__cosf(d * p1) + __sinf(d * p2));
}

__global__ void __launch_bounds__(NTH, 1)
fused_timestep_mlp_v15(const float* __restrict__ t,
                       const float* __restrict__ W1,
                       const float* __restrict__ b1,
                       const float* __restrict__ W2,
                       const float* __restrict__ b2,
                       float* __restrict__ out,
                       int n_chunks) {
    extern __shared__ char sm[];
    const uint32_t sb = smem_u32(sm);
    const int tid = threadIdx.x;
    const int wid = tid >> 5;
    const int lane = tid & 31;

    // ---- weight init: packed core-matrix fp16 tiles; biases ----
    for (int e = tid * 4; e < DIM * DIM; e += NTH * 4) {
        const int row = e >> 7, k = e & 127;
        const float4 v1 = *(const float4*)(W1 + e);
        *(uint32_t*)(sm + OFF_W1 + w_off(row, k))     = pack2h(v1.x, v1.y);
        *(uint32_t*)(sm + OFF_W1 + w_off(row, k + 2)) = pack2h(v1.z, v1.w);
        const float4 v2 = *(const float4*)(W2 + e);
        *(uint32_t*)(sm + OFF_W2 + w_off(row, k))     = pack2h(v2.x, v2.y);
        *(uint32_t*)(sm + OFF_W2 + w_off(row, k + 2)) = pack2h(v2.z, v2.w);
    }
    if (tid < 128)      ((float*)(sm + OFF_B1))[tid] = b1[tid];
    else if (tid < 256) ((float*)(sm + OFF_B2))[tid - 128] = b2[tid - 128];
    __syncthreads();  // only sync in the kernel

    const float* sB1 = (const float*)(sm + OFF_B1);
    const float* sB2 = (const float*)(sm + OFF_B2);

    // lane geometry
    const int r0 = lane >> 2;        // frag row (and +8)
    const int kp = (lane & 3) * 2;   // frag col-pair base
    const int g = lane >> 3, i = lane & 7;
    // per-lane offset into the packed-tile grid for ldsm4 of a 16n x 16k block:
    // matrix g: kt-offset (g&1) tiles (=2048B), nt-offset (g>>1) tiles (=128B), row i (16B)
    const uint32_t tileOff = ((uint32_t)(g & 1) << 11) | ((uint32_t)(g >> 1) << 7)
                           | ((uint32_t)i << 4);

    for (int chunk = blockIdx.x * WARPS + wid; chunk < n_chunks;
         chunk += gridDim.x * WARPS) {
        const int rowBase = chunk * 16;

        // ---- emb A-frags, built once: ea[ks][4] ----
        uint32_t ea[8][4];
        {
            const float tv0 = t[rowBase + r0];
            const float tv1 = t[rowBase + r0 + 8];
            const float p10 = tv0 * (PI_F / 128.0f), p20 = (1.0f - tv0) * (PI_F / 128.0f);
            const float p11 = tv1 * (PI_F / 128.0f), p21 = (1.0f - tv1) * (PI_F / 128.0f);
#pragma unroll
            for (int ks = 0; ks < 8; ++ks) {
                const float dA = (float)(ks * 16 + kp), dB = dA + 1.0f;
                const float dC = dA + 8.0f,             dD = dA + 9.0f;
                ea[ks][0] = pack2h(emb_f(tv0, p10, p20, dA), emb_f(tv0, p10, p20, dB));
                ea[ks][1] = pack2h(emb_f(tv1, p11, p21, dA), emb_f(tv1, p11, p21, dB));
                ea[ks][2] = pack2h(emb_f(tv0, p10, p20, dC), emb_f(tv0, p10, p20, dD));
                ea[ks][3] = pack2h(emb_f(tv1, p11, p21, dC), emb_f(tv1, p11, p21, dD));
            }
        }

        uint32_t ha[8][4];   // layer-2 A-frags
        float acc[8][4];     // reused across all 4 passes

        // ======== GEMM1: two 64-col passes ========
#pragma unroll
        for (int nh = 0; nh < 2; ++nh) {
#pragma unroll
            for (int nt = 0; nt < 8; ++nt)
#pragma unroll
                for (int q = 0; q < 4; ++q) acc[nt][q] = 0.0f;

#pragma unroll
            for (int ks = 0; ks < 8; ++ks) {
#pragma unroll
                for (int np = 0; np < 4; ++np) {
                    const int npg = nh * 4 + np;   // global 16-col group
                    uint32_t b[4];
                    ldsm4(b[0], b[1], b[2], b[3],
                          sb + OFF_W1 + ((uint32_t)ks << 12) + ((uint32_t)npg << 8) + tileOff);
                    mma16816(acc[2 * np],     ea[ks], b[0], b[1]);
                    mma16816(acc[2 * np + 1], ea[ks], b[2], b[3]);
                }
            }

            // convert this 64-col half: bias + silu(f16x2 tanh) -> ha[nh*4 + j]
#pragma unroll
            for (int j = 0; j < 4; ++j) {
                const int colbase = nh * 64 + j * 16;
                const float2 bA = *(const float2*)(sB1 + colbase + kp);
                const float2 bB = *(const float2*)(sB1 + colbase + 8 + kp);
                const float* c0 = acc[2 * j];
                const float* c1 = acc[2 * j + 1];
                ha[nh * 4 + j][0] = h2_silu(c0[0] + bA.x, c0[1] + bA.y);
                ha[nh * 4 + j][1] = h2_silu(c0[2] + bA.x, c0[3] + bA.y);
                ha[nh * 4 + j][2] = h2_silu(c1[0] + bB.x, c1[1] + bB.y);
                ha[nh * 4 + j][3] = h2_silu(c1[2] + bB.x, c1[3] + bB.y);
            }
        }

        // ======== GEMM2: two 64-col passes ========
        float* o0 = out + (size_t)(rowBase + r0) * DIM;
        float* o1 = out + (size_t)(rowBase + r0 + 8) * DIM;
#pragma unroll
        for (int nh = 0; nh < 2; ++nh) {
#pragma unroll
            for (int nt = 0; nt < 8; ++nt)
#pragma unroll
                for (int q = 0; q < 4; ++q) acc[nt][q] = 0.0f;

#pragma unroll
            for (int ks = 0; ks < 8; ++ks) {
#pragma unroll
                for (int np = 0; np < 4; ++np) {
                    const int npg = nh * 4 + np;
                    uint32_t b[4];
                    ldsm4(b[0], b[1], b[2], b[3],
                          sb + OFF_W2 + ((uint32_t)ks << 12) + ((uint32_t)npg << 8) + tileOff);
                    mma16816(acc[2 * np],     ha[ks], b[0], b[1]);
                    mma16816(acc[2 * np + 1], ha[ks], b[2], b[3]);
                }
            }

            // store this 64-col half: bias + silu (fp32) -> gmem
#pragma unroll
            for (int nt = 0; nt < 8; ++nt) {
                const int c = nh * 64 + nt * 8 + kp;
                const float2 bb = *(const float2*)(sB2 + c);
                const float* a4 = acc[nt];
                *(float2*)(o0 + c) = make_float2(silu_f(a4[0] + bb.x), silu_f(a4[1] + bb.y));
                *(float2*)(o1 + c) = make_float2(silu_f(a4[2] + bb.x), silu_f(a4[3] + bb.y));
            }
        }
    }
}

extern "C" void kernel_launch(void* const* d_in, const int* in_sizes, int n_in,
                              void* d_out, int out_size) {
    const float* t  = (const float*)d_in[0];
    const float* W1 = (const float*)d_in[1];
    const float* b1 = (const float*)d_in[2];
    const float* W2 = (const float*)d_in[3];
    const float* b2 = (const float*)d_in[4];
    float* out = (float*)d_out;

    const int B = in_sizes[0];
    const int n_chunks = B / 16;

    int nsm = 148;
    cudaDeviceGetAttribute(&nsm, cudaDevAttrMultiProcessorCount, 0);

    cudaFuncSetAttribute(fused_timestep_mlp_v15,
                         cudaFuncAttributeMaxDynamicSharedMemorySize, SMEM_TOTAL);

    fused_timestep_mlp_v15<<<nsm, NTH, SMEM_TOTAL>>>(t, W1, b1, W2, b2, out, n_chunks);
}

// round 16
// speedup vs baseline: 1.4969x; 1.0696x over previous
#include <cuda_runtime.h>
#include <cuda_fp16.h>
#include <cstdint>

#define DIM 128
#define NTH 512
#define WARPS 16
#define PI_F 3.14159265358979323846f

// ---- smem: two packed-tile fp16 weight tiles (32 KB each) + biases ----
#define OFF_W1  0
#define OFF_W2  32768
#define OFF_B1  65536
#define OFF_B2  66048
#define SMEM_TOTAL 66560

// packed core-matrix layout: W[128n][128k] fp16 as 16x16 grid of 8x8 matrices;
// matrix (nt,kt) contiguous 128B at ((kt*16)+nt)*128; within: r*16 + c*2.
__device__ __forceinline__ uint32_t w_off(int n, int k) {
    return (uint32_t)((((k >> 3) << 4) + (n >> 3)) * 128 + (n & 7) * 16 + (k & 7) * 2);
}

__device__ __forceinline__ uint32_t smem_u32(const void* p) {
    uint32_t a;
    asm("{ .reg .u64 t; cvta.to.shared.u64 t, %1; cvt.u32.u64 %0, t; }" : "=r"(a) : "l"(p));
    return a;
}

__device__ __forceinline__ void ldsm4(uint32_t& r0, uint32_t& r1, uint32_t& r2, uint32_t& r3,
                                      uint32_t addr) {
    asm volatile("ldmatrix.sync.aligned.m8n8.x4.shared.b16 {%0,%1,%2,%3}, [%4];"
                 : "=r"(r0), "=r"(r1), "=r"(r2), "=r"(r3) : "r"(addr));
}

__device__ __forceinline__ void mma16816(float* c, const uint32_t* a, uint32_t b0, uint32_t b1) {
    asm volatile(
        "mma.sync.aligned.m16n8k16.row.col.f32.f16.f16.f32 "
        "{%0,%1,%2,%3}, {%4,%5,%6,%7}, {%8,%9}, {%0,%1,%2,%3};"
        : "+f"(c[0]), "+f"(c[1]), "+f"(c[2]), "+f"(c[3])
        : "r"(a[0]), "r"(a[1]), "r"(a[2]), "r"(a[3]), "r"(b0), "r"(b1));
}

__device__ __forceinline__ uint32_t pack2h(float x0, float x1) {
    uint32_t r;
    asm("cvt.rn.f16x2.f32 %0, %1, %2;" : "=r"(r) : "f"(x1), "f"(x0));
    return r;
}

// silu on packed fp16 pair via tanh.approx.f16x2 (hidden layer)
__device__ __forceinline__ uint32_t h2_silu(float z0, float z1) {
    const uint32_t zh = pack2h(z0, z1);
    const uint32_t half2c = 0x38003800u;  // (0.5, 0.5) fp16x2
    uint32_t t, s, r;
    asm("mul.rn.f16x2 %0, %1, %2;" : "=r"(t) : "r"(zh), "r"(half2c));
    asm("tanh.approx.f16x2 %0, %1;" : "=r"(t) : "r"(t));
    asm("fma.rn.f16x2 %0, %1, %2, %2;" : "=r"(s) : "r"(t), "r"(half2c));
    asm("mul.rn.f16x2 %0, %1, %2;" : "=r"(r) : "r"(zh), "r"(s));
    return r;
}

// fp32 silu via tanh.approx.f32 (output layer): z*0.5*(1+tanh(z/2))
__device__ __forceinline__ float silu_f(float z) {
    float th;
    const float zh = 0.5f * z;
    asm("tanh.approx.f32 %0, %1;" : "=f"(th) : "f"(zh));
    return zh * (1.0f + th);
}

__global__ void __launch_bounds__(NTH, 1)
fused_timestep_mlp_v16(const float* __restrict__ t,
                       const float* __restrict__ W1,
                       const float* __restrict__ b1,
                       const float* __restrict__ W2,
                       const float* __restrict__ b2,
                       float* __restrict__ out,
                       int n_chunks) {
    extern __shared__ char sm[];
    const uint32_t sb = smem_u32(sm);
    const int tid = threadIdx.x;
    const int wid = tid >> 5;
    const int lane = tid & 31;

    // ---- weight init: packed core-matrix fp16 tiles; biases ----
    for (int e = tid * 4; e < DIM * DIM; e += NTH * 4) {
        const int row = e >> 7, k = e & 127;
        const float4 v1 = *(const float4*)(W1 + e);
        *(uint32_t*)(sm + OFF_W1 + w_off(row, k))     = pack2h(v1.x, v1.y);
        *(uint32_t*)(sm + OFF_W1 + w_off(row, k + 2)) = pack2h(v1.z, v1.w);
        const float4 v2 = *(const float4*)(W2 + e);
        *(uint32_t*)(sm + OFF_W2 + w_off(row, k))     = pack2h(v2.x, v2.y);
        *(uint32_t*)(sm + OFF_W2 + w_off(row, k + 2)) = pack2h(v2.z, v2.w);
    }
    if (tid < 128)      ((float*)(sm + OFF_B1))[tid] = b1[tid];
    else if (tid < 256) ((float*)(sm + OFF_B2))[tid - 128] = b2[tid - 128];
    __syncthreads();  // only sync in the kernel

    const float* sB1 = (const float*)(sm + OFF_B1);
    const float* sB2 = (const float*)(sm + OFF_B2);

    // lane geometry
    const int r0 = lane >> 2;        // frag row (and +8)
    const int kp = (lane & 3) * 2;   // frag col-pair base
    const int g = lane >> 3, i = lane & 7;
    const uint32_t tileOff = ((uint32_t)(g & 1) << 11) | ((uint32_t)(g >> 1) << 7)
                           | ((uint32_t)i << 4);

    for (int chunk = blockIdx.x * WARPS + wid; chunk < n_chunks;
         chunk += gridDim.x * WARPS) {
        const int rowBase = chunk * 16;

        // ---- emb A-frags via rotation recurrence: ea[ks][4] ----
        uint32_t ea[8][4];
        {
            // per row u: F1 chains (angle step p1, cos used) at d=kp and kp+8;
            //            F2 chains (step p2, sin used). All scaled by tv.
            float C1a[2], S1a[2], C1b[2], S1b[2];
            float C2a[2], S2a[2], C2b[2], S2b[2];
            float R1c[2], R1s[2], R2c[2], R2s[2];   // rot by 16 steps
            float q1c[2], q1s[2], q2c[2], q2s[2];   // rot by 1 step
#pragma unroll
            for (int u = 0; u < 2; ++u) {
                const float tv = t[rowBase + r0 + u * 8];
                const float p1 = tv * (PI_F / 128.0f);
                const float p2 = (1.0f - tv) * (PI_F / 128.0f);
                const float dk = (float)kp;
                C1a[u] = tv * __cosf(dk * p1);          S1a[u] = tv * __sinf(dk * p1);
                C1b[u] = tv * __cosf((dk + 8.0f) * p1); S1b[u] = tv * __sinf((dk + 8.0f) * p1);
                C2a[u] = tv * __cosf(dk * p2);          S2a[u] = tv * __sinf(dk * p2);
                C2b[u] = tv * __cosf((dk + 8.0f) * p2); S2b[u] = tv * __sinf((dk + 8.0f) * p2);
                R1c[u] = __cosf(16.0f * p1); R1s[u] = __sinf(16.0f * p1);
                R2c[u] = __cosf(16.0f * p2); R2s[u] = __sinf(16.0f * p2);
                q1c[u] = __cosf(p1);         q1s[u] = __sinf(p1);
                q2c[u] = __cosf(p2);         q2s[u] = __sinf(p2);
            }
#pragma unroll
            for (int ks = 0; ks < 8; ++ks) {
#pragma unroll
                for (int u = 0; u < 2; ++u) {
                    // elements at d = kp, kp+1 (from a-chains), kp+8, kp+9 (b-chains)
                    const float e0 = C1a[u] + S2a[u];
                    const float e1 = (C1a[u] * q1c[u] - S1a[u] * q1s[u])
                                   + (S2a[u] * q2c[u] + C2a[u] * q2s[u]);
                    const float e8 = C1b[u] + S2b[u];
                    const float e9 = (C1b[u] * q1c[u] - S1b[u] * q1s[u])
                                   + (S2b[u] * q2c[u] + C2b[u] * q2s[u]);
                    ea[ks][u]     = pack2h(e0, e1);
                    ea[ks][2 + u] = pack2h(e8, e9);
                    // advance all 4 chains of this row by 16 steps
                    float nc, ns;
                    nc = C1a[u] * R1c[u] - S1a[u] * R1s[u];
                    ns = S1a[u] * R1c[u] + C1a[u] * R1s[u];
                    C1a[u] = nc; S1a[u] = ns;
                    nc = C1b[u] * R1c[u] - S1b[u] * R1s[u];
                    ns = S1b[u] * R1c[u] + C1b[u] * R1s[u];
                    C1b[u] = nc; S1b[u] = ns;
                    nc = C2a[u] * R2c[u] - S2a[u] * R2s[u];
                    ns = S2a[u] * R2c[u] + C2a[u] * R2s[u];
                    C2a[u] = nc; S2a[u] = ns;
                    nc = C2b[u] * R2c[u] - S2b[u] * R2s[u];
                    ns = S2b[u] * R2c[u] + C2b[u] * R2s[u];
                    C2b[u] = nc; S2b[u] = ns;
                }
            }
        }

        uint32_t ha[8][4];   // layer-2 A-frags
        float acc[8][4];     // reused across all 4 passes

        // ======== GEMM1: two 64-col passes ========
#pragma unroll
        for (int nh = 0; nh < 2; ++nh) {
#pragma unroll
            for (int nt = 0; nt < 8; ++nt)
#pragma unroll
                for (int q = 0; q < 4; ++q) acc[nt][q] = 0.0f;

#pragma unroll
            for (int ks = 0; ks < 8; ++ks) {
#pragma unroll
                for (int np = 0; np < 4; ++np) {
                    const int npg = nh * 4 + np;
                    uint32_t b[4];
                    ldsm4(b[0], b[1], b[2], b[3],
                          sb + OFF_W1 + ((uint32_t)ks << 12) + ((uint32_t)npg << 8) + tileOff);
                    mma16816(acc[2 * np],     ea[ks], b[0], b[1]);
                    mma16816(acc[2 * np + 1], ea[ks], b[2], b[3]);
                }
            }

            // convert this 64-col half: bias + silu(f16x2 tanh) -> ha[nh*4 + j]
#pragma unroll
            for (int j = 0; j < 4; ++j) {
                const int colbase = nh * 64 + j * 16;
                const float2 bA = *(const float2*)(sB1 + colbase + kp);
                const float2 bB = *(const float2*)(sB1 + colbase + 8 + kp);
                const float* c0 = acc[2 * j];
                const float* c1 = acc[2 * j + 1];
                ha[nh * 4 + j][0] = h2_silu(c0[0] + bA.x, c0[1] + bA.y);
                ha[nh * 4 + j][1] = h2_silu(c0[2] + bA.x, c0[3] + bA.y);
                ha[nh * 4 + j][2] = h2_silu(c1[0] + bB.x, c1[1] + bB.y);
                ha[nh * 4 + j][3] = h2_silu(c1[2] + bB.x, c1[3] + bB.y);
            }
        }

        // ======== GEMM2: two 64-col passes ========
        float* o0 = out + (size_t)(rowBase + r0) * DIM;
        float* o1 = out + (size_t)(rowBase + r0 + 8) * DIM;
#pragma unroll
        for (int nh = 0; nh < 2; ++nh) {
#pragma unroll
            for (int nt = 0; nt < 8; ++nt)
#pragma unroll
                for (int q = 0; q < 4; ++q) acc[nt][q] = 0.0f;

#pragma unroll
            for (int ks = 0; ks < 8; ++ks) {
#pragma unroll
                for (int np = 0; np < 4; ++np) {
                    const int npg = nh * 4 + np;
                    uint32_t b[4];
                    ldsm4(b[0], b[1], b[2], b[3],
                          sb + OFF_W2 + ((uint32_t)ks << 12) + ((uint32_t)npg << 8) + tileOff);
                    mma16816(acc[2 * np],     ha[ks], b[0], b[1]);
                    mma16816(acc[2 * np + 1], ha[ks], b[2], b[3]);
                }
            }

            // store this 64-col half: bias + silu (tanh.f32) -> gmem
#pragma unroll
            for (int nt = 0; nt < 8; ++nt) {
                const int c = nh * 64 + nt * 8 + kp;
                const float2 bb = *(const float2*)(sB2 + c);
                const float* a4 = acc[nt];
                *(float2*)(o0 + c) = make_float2(silu_f(a4[0] + bb.x), silu_f(a4[1] + bb.y));
                *(float2*)(o1 + c) = make_float2(silu_f(a4[2] + bb.x), silu_f(a4[3] + bb.y));
            }
        }
    }
}

extern "C" void kernel_launch(void* const* d_in, const int* in_sizes, int n_in,
                              void* d_out, int out_size) {
    const float* t  = (const float*)d_in[0];
    const float* W1 = (const float*)d_in[1];
    const float* b1 = (const float*)d_in[2];
    const float* W2 = (const float*)d_in[3];
    const float* b2 = (const float*)d_in[4];
    float* out = (float*)d_out;

    const int B = in_sizes[0];
    const int n_chunks = B / 16;

    int nsm = 148;
    cudaDeviceGetAttribute(&nsm, cudaDevAttrMultiProcessorCount, 0);

    cudaFuncSetAttribute(fused_timestep_mlp_v16,
                         cudaFuncAttributeMaxDynamicSharedMemorySize, SMEM_TOTAL);

    fused_timestep_mlp_v16<<<nsm, NTH, SMEM_TOTAL>>>(t, W1, b1, W2, b2, out, n_chunks);
}